// round 2
// baseline (speedup 1.0000x reference)
#include <cuda_runtime.h>
#include <float.h>

// Chamfer distance, B=4, N=M=4096, D=3.
// dist(p,g) = ||p||^2 + ||g||^2 - 2 p.g ; inner loop evaluates
// d' = (-2p).g + ||g||^2 for TWO g points at once via packed fma.rn.f32x2.
// Shared layout per point-pair p: sdst[2p] = {x0|x1, y0|y1}, sdst[2p+1] = {z0|z1, w0|w1}
// where w = ||g||^2.  ||p||^2 added once after the min (doesn't affect argmin).

#define BATCH 4
#define NPTS  4096
#define NPAIRS (NPTS / 2)
#define TPB   256
#define CHUNKS (NPTS / TPB)              // 16 blocks per (batch, dir)
#define NPARTIALS (CHUNKS * BATCH * 2)   // 128

__device__ float g_partials[NPARTIALS];

typedef unsigned long long u64;

__device__ __forceinline__ u64 pk(float a, float b) {
    u64 r;
    asm("mov.b64 %0, {%1, %2};" : "=l"(r) : "f"(a), "f"(b));
    return r;
}
__device__ __forceinline__ void upk(u64 v, float& lo, float& hi) {
    asm("mov.b64 {%0, %1}, %2;" : "=f"(lo), "=f"(hi) : "l"(v));
}
__device__ __forceinline__ u64 fma2(u64 a, u64 b, u64 c) {
    u64 d;
    asm("fma.rn.f32x2 %0, %1, %2, %3;" : "=l"(d) : "l"(a), "l"(b), "l"(c));
    return d;
}

__global__ void __launch_bounds__(TPB) chamfer_kernel(
    const float* __restrict__ recon,
    const float* __restrict__ gt)
{
    extern __shared__ ulonglong2 sdst[];   // 4096 entries x 16B = 64 KB

    const int bx  = blockIdx.x;   // src chunk
    const int b   = blockIdx.y;   // batch
    const int dir = blockIdx.z;   // 0: recon->gt, 1: gt->recon
    const int tid = threadIdx.x;

    const float* src = (dir == 0) ? recon : gt;
    const float* dst = (dir == 0) ? gt : recon;
    const float* dstb = dst + (size_t)b * NPTS * 3;

    // Prologue: cache opposite set as packed pairs (+ squared norms).
    // Each thread handles 4 consecutive points per step (12 floats = 3 float4,
    // 48B-aligned since base offset is 48*t bytes).
    for (int base = 4 * tid; base < NPTS; base += 4 * TPB) {
        const float4* gp = (const float4*)(dstb + 3 * base);
        float4 f0 = gp[0];   // x0 y0 z0 x1
        float4 f1 = gp[1];   // y1 z1 x2 y2
        float4 f2 = gp[2];   // z2 x3 y3 z3
        float w0 = fmaf(f0.x, f0.x, fmaf(f0.y, f0.y, f0.z * f0.z));
        float w1 = fmaf(f0.w, f0.w, fmaf(f1.x, f1.x, f1.y * f1.y));
        float w2 = fmaf(f1.z, f1.z, fmaf(f1.w, f1.w, f2.x * f2.x));
        float w3 = fmaf(f2.y, f2.y, fmaf(f2.z, f2.z, f2.w * f2.w));
        // pair (p0,p1) -> sdst[base], sdst[base+1]
        sdst[base + 0] = make_ulonglong2(pk(f0.x, f0.w), pk(f0.y, f1.x));
        sdst[base + 1] = make_ulonglong2(pk(f0.z, f1.y), pk(w0, w1));
        // pair (p2,p3) -> sdst[base+2], sdst[base+3]
        sdst[base + 2] = make_ulonglong2(pk(f1.z, f2.y), pk(f1.w, f2.z));
        sdst[base + 3] = make_ulonglong2(pk(f2.x, f2.w), pk(w2, w3));
    }
    __syncthreads();

    // Each thread owns one source point.
    const int i = bx * TPB + tid;
    const float* sp = src + ((size_t)b * NPTS + i) * 3;
    const float px = sp[0], py = sp[1], pz = sp[2];
    const u64 qx = pk(-2.0f * px, -2.0f * px);
    const u64 qy = pk(-2.0f * py, -2.0f * py);
    const u64 qz = pk(-2.0f * pz, -2.0f * pz);
    const float np = fmaf(px, px, fmaf(py, py, pz * pz));

    float mlo = FLT_MAX, mhi = FLT_MAX;

    #pragma unroll 8
    for (int p = 0; p < NPAIRS; ++p) {
        ulonglong2 A = sdst[2 * p];       // {xx, yy}
        ulonglong2 B = sdst[2 * p + 1];   // {zz, ww}
        u64 d = fma2(qx, A.x, fma2(qy, A.y, fma2(qz, B.x, B.y)));
        float dlo, dhi;
        upk(d, dlo, dhi);
        mlo = fminf(mlo, dlo);
        mhi = fminf(mhi, dhi);
    }

    float m = fminf(mlo, mhi) + np;

    // Deterministic block sum (fixed-order tree), reusing smem.
    __syncthreads();
    float* sred = (float*)sdst;
    sred[tid] = m;
    __syncthreads();
    #pragma unroll
    for (int s = TPB / 2; s > 0; s >>= 1) {
        if (tid < s) sred[tid] += sred[tid + s];
        __syncthreads();
    }
    if (tid == 0)
        g_partials[bx + CHUNKS * (b + BATCH * dir)] = sred[0];
}

__global__ void __launch_bounds__(NPARTIALS) finalize_kernel(float* out)
{
    __shared__ float s[NPARTIALS];
    const int tid = threadIdx.x;
    s[tid] = g_partials[tid];
    __syncthreads();
    #pragma unroll
    for (int st = NPARTIALS / 2; st > 0; st >>= 1) {
        if (tid < st) s[tid] += s[tid + st];
        __syncthreads();
    }
    if (tid == 0)
        out[0] = s[0] / (float)(2 * BATCH * NPTS);  // (mean1 + mean2) / 2
}

extern "C" void kernel_launch(void* const* d_in, const int* in_sizes, int n_in,
                              void* d_out, int out_size)
{
    const float* recon = (const float*)d_in[0];
    const float* gt    = (const float*)d_in[1];
    float* out = (float*)d_out;

    const int smem = NPTS * (int)sizeof(ulonglong2);  // 64 KB
    cudaFuncSetAttribute(chamfer_kernel,
                         cudaFuncAttributeMaxDynamicSharedMemorySize, smem);

    dim3 grid(CHUNKS, BATCH, 2);
    chamfer_kernel<<<grid, TPB, smem>>>(recon, gt);
    finalize_kernel<<<1, NPARTIALS>>>(out);
}

// round 3
// speedup vs baseline: 1.2381x; 1.2381x over previous
#include <cuda_runtime.h>
#include <float.h>

// Chamfer distance, B=4, N=M=4096, D=3 — fused single-kernel version.
// dist(p,g) = ||p||^2 + ||g||^2 - 2 p.g ; inner loop: d' = (-2p).g + ||g||^2
// (3 FFMA/pair, seeded by precomputed ||g||^2 in .w; FMNMX rides the ALU pipe).
// ||p||^2 added once after the min. Last CTA (atomic counter) does the final
// fixed-order sum -> deterministic, graph-replay-safe (counter self-resets).

#define BATCH 4
#define NPTS  4096
#define TPB   256
#define CHUNKS (NPTS / TPB)              // 16
#define NCTAS (CHUNKS * BATCH * 2)       // 128 CTAs

__device__ float g_partials[NCTAS];
__device__ unsigned int g_count = 0;

__global__ void __launch_bounds__(TPB) chamfer_fused_kernel(
    const float* __restrict__ recon,
    const float* __restrict__ gt,
    float* __restrict__ out)
{
    extern __shared__ float4 sdst[];   // 4096 x float4 = 64 KB

    const int bx  = blockIdx.x;   // src chunk
    const int b   = blockIdx.y;   // batch
    const int dir = blockIdx.z;   // 0: recon->gt, 1: gt->recon
    const int tid = threadIdx.x;

    const float* src = (dir == 0) ? recon : gt;
    const float* dst = (dir == 0) ? gt : recon;
    const float* dstb = dst + (size_t)b * NPTS * 3;

    // Prologue: cache opposite set (+ squared norm) in shared memory.
    // 4 points = 3 float4 per step; base byte offset 48*t keeps 16B alignment.
    for (int base = 4 * tid; base < NPTS; base += 4 * TPB) {
        const float4* gp = (const float4*)(dstb + 3 * base);
        float4 f0 = gp[0];   // x0 y0 z0 x1
        float4 f1 = gp[1];   // y1 z1 x2 y2
        float4 f2 = gp[2];   // z2 x3 y3 z3
        sdst[base + 0] = make_float4(f0.x, f0.y, f0.z,
                                     fmaf(f0.x, f0.x, fmaf(f0.y, f0.y, f0.z * f0.z)));
        sdst[base + 1] = make_float4(f0.w, f1.x, f1.y,
                                     fmaf(f0.w, f0.w, fmaf(f1.x, f1.x, f1.y * f1.y)));
        sdst[base + 2] = make_float4(f1.z, f1.w, f2.x,
                                     fmaf(f1.z, f1.z, fmaf(f1.w, f1.w, f2.x * f2.x)));
        sdst[base + 3] = make_float4(f2.y, f2.z, f2.w,
                                     fmaf(f2.y, f2.y, fmaf(f2.z, f2.z, f2.w * f2.w)));
    }
    __syncthreads();

    // Each thread owns one source point.
    const int i = bx * TPB + tid;
    const float* sp = src + ((size_t)b * NPTS + i) * 3;
    const float px = sp[0], py = sp[1], pz = sp[2];
    const float qx = -2.0f * px, qy = -2.0f * py, qz = -2.0f * pz;
    const float np = fmaf(px, px, fmaf(py, py, pz * pz));

    float m0 = FLT_MAX, m1 = FLT_MAX, m2 = FLT_MAX, m3 = FLT_MAX;

    #pragma unroll 2
    for (int j = 0; j < NPTS; j += 8) {
        float4 g0 = sdst[j + 0];
        float4 g1 = sdst[j + 1];
        float4 g2 = sdst[j + 2];
        float4 g3 = sdst[j + 3];
        float4 g4 = sdst[j + 4];
        float4 g5 = sdst[j + 5];
        float4 g6 = sdst[j + 6];
        float4 g7 = sdst[j + 7];

        float d0 = fmaf(qx, g0.x, fmaf(qy, g0.y, fmaf(qz, g0.z, g0.w)));
        float d1 = fmaf(qx, g1.x, fmaf(qy, g1.y, fmaf(qz, g1.z, g1.w)));
        float d2 = fmaf(qx, g2.x, fmaf(qy, g2.y, fmaf(qz, g2.z, g2.w)));
        float d3 = fmaf(qx, g3.x, fmaf(qy, g3.y, fmaf(qz, g3.z, g3.w)));
        float d4 = fmaf(qx, g4.x, fmaf(qy, g4.y, fmaf(qz, g4.z, g4.w)));
        float d5 = fmaf(qx, g5.x, fmaf(qy, g5.y, fmaf(qz, g5.z, g5.w)));
        float d6 = fmaf(qx, g6.x, fmaf(qy, g6.y, fmaf(qz, g6.z, g6.w)));
        float d7 = fmaf(qx, g7.x, fmaf(qy, g7.y, fmaf(qz, g7.z, g7.w)));

        m0 = fminf(m0, d0);
        m1 = fminf(m1, d1);
        m2 = fminf(m2, d2);
        m3 = fminf(m3, d3);
        m0 = fminf(m0, d4);
        m1 = fminf(m1, d5);
        m2 = fminf(m2, d6);
        m3 = fminf(m3, d7);
    }

    float m = fminf(fminf(m0, m1), fminf(m2, m3)) + np;

    // Deterministic block sum (fixed-order tree), reusing smem.
    __syncthreads();
    float* sred = (float*)sdst;
    sred[tid] = m;
    __syncthreads();
    #pragma unroll
    for (int s = TPB / 2; s > 0; s >>= 1) {
        if (tid < s) sred[tid] += sred[tid + s];
        __syncthreads();
    }

    // Publish partial and elect the last CTA to finalize.
    __shared__ unsigned int s_last;
    if (tid == 0) {
        g_partials[bx + CHUNKS * (b + BATCH * dir)] = sred[0];
        __threadfence();
        unsigned int old = atomicAdd(&g_count, 1u);
        s_last = (old == NCTAS - 1) ? 1u : 0u;
    }
    __syncthreads();

    if (s_last) {
        __threadfence();  // acquire: all partials visible
        float v = (tid < NCTAS) ? g_partials[tid] : 0.0f;
        sred[tid] = v;
        __syncthreads();
        #pragma unroll
        for (int s = TPB / 2; s > 0; s >>= 1) {
            if (tid < s) sred[tid] += sred[tid + s];
            __syncthreads();
        }
        if (tid == 0) {
            out[0] = sred[0] / (float)(2 * BATCH * NPTS);
            g_count = 0;   // reset for next graph replay
        }
    }
}

extern "C" void kernel_launch(void* const* d_in, const int* in_sizes, int n_in,
                              void* d_out, int out_size)
{
    const float* recon = (const float*)d_in[0];
    const float* gt    = (const float*)d_in[1];
    float* out = (float*)d_out;

    const int smem = NPTS * (int)sizeof(float4);  // 64 KB
    cudaFuncSetAttribute(chamfer_fused_kernel,
                         cudaFuncAttributeMaxDynamicSharedMemorySize, smem);

    dim3 grid(CHUNKS, BATCH, 2);
    chamfer_fused_kernel<<<grid, TPB, smem>>>(recon, gt, out);
}